// round 9
// baseline (speedup 1.0000x reference)
#include <cuda_runtime.h>
#include <cstdint>

#define BATCH 16384
#define NB 8
#define BIN 512
#define BOUT 512
#define ROWSTRIDE 4096

#define BM 128
#define BN 256
#define BK 32
#define STAGES 3
#define THREADS 256
#define KITERS (BIN / BK)            // 16

#define A_STAGE_BYTES (BM * BK * 4)  // 16384
#define B_STAGE_BYTES (BN * BK * 4)  // 32768
#define STAGE_BYTES (A_STAGE_BYTES + B_STAGE_BYTES)
#define SMEM_BYTES (STAGES * STAGE_BYTES)   // 147456

// W pre-rounded to tf32-RN (fp32 storage): no in-loop cvts, better accuracy
// than double truncation.
__device__ float g_Wtf[NB * BOUT * BIN];

__device__ __forceinline__ uint32_t swz(uint32_t off) {
    return off ^ ((off >> 3) & 0x70);   // 128B-row xor swizzle
}

__device__ __forceinline__ void ldsm_x4(uint32_t* r, uint32_t addr) {
    asm volatile("ldmatrix.sync.aligned.m8n8.x4.shared.b16 {%0,%1,%2,%3}, [%4];"
                 : "=r"(r[0]), "=r"(r[1]), "=r"(r[2]), "=r"(r[3]) : "r"(addr));
}

__device__ __forceinline__ void cp16(uint32_t saddr, const void* g) {
    asm volatile("cp.async.cg.shared.global [%0], [%1], 16;" :: "r"(saddr), "l"(g));
}
__device__ __forceinline__ void cp_commit() {
    asm volatile("cp.async.commit_group;" ::: "memory");
}
template <int N>
__device__ __forceinline__ void cp_wait() {
    asm volatile("cp.async.wait_group %0;" :: "n"(N) : "memory");
}

__device__ __forceinline__ void mma_tf32(float* c, const uint32_t* a,
                                         uint32_t b0, uint32_t b1) {
    asm volatile(
        "mma.sync.aligned.m16n8k8.row.col.f32.tf32.tf32.f32 "
        "{%0,%1,%2,%3}, {%4,%5,%6,%7}, {%8,%9}, {%0,%1,%2,%3};"
        : "+f"(c[0]), "+f"(c[1]), "+f"(c[2]), "+f"(c[3])
        : "r"(a[0]), "r"(a[1]), "r"(a[2]), "r"(a[3]), "r"(b0), "r"(b1));
}

// ---- W pre-rounding: fp32 -> tf32-RN bits (fp32 storage) ----
__global__ void round_w_kernel(const float* __restrict__ W) {
    int i = (blockIdx.x * blockDim.x + threadIdx.x) * 4;
    float4 v = *reinterpret_cast<const float4*>(W + i);
    uint32_t r0, r1, r2, r3;
    asm("cvt.rna.tf32.f32 %0, %1;" : "=r"(r0) : "f"(v.x));
    asm("cvt.rna.tf32.f32 %0, %1;" : "=r"(r1) : "f"(v.y));
    asm("cvt.rna.tf32.f32 %0, %1;" : "=r"(r2) : "f"(v.z));
    asm("cvt.rna.tf32.f32 %0, %1;" : "=r"(r3) : "f"(v.w));
    float4 o = make_float4(__uint_as_float(r0), __uint_as_float(r1),
                           __uint_as_float(r2), __uint_as_float(r3));
    *reinterpret_cast<float4*>(g_Wtf + i) = o;
}

__global__ void __launch_bounds__(THREADS, 1)
block_linear_tf32_big(const float* __restrict__ x,
                      const float* __restrict__ bias,
                      float* __restrict__ out)
{
    extern __shared__ uint8_t smem[];
    const uint32_t smem_u32 = (uint32_t)__cvta_generic_to_shared(smem);

    const int n0 = blockIdx.x * BN;        // n fastest -> L2 x-slice reuse
    const int g  = blockIdx.y;
    const int m0 = blockIdx.z * BM;

    const int tid  = threadIdx.x;
    const int warp = tid >> 5;
    const int lane = tid & 31;
    const int grp  = lane >> 2;
    const int tig  = lane & 3;

    const int wm = (warp & 1) * 64;        // 2 m-groups (64 rows each)
    const int wn = (warp >> 1) * 64;       // 4 n-groups (64 cols each)

    const int lrow   = lane & 15;
    const int lchunk = (lane >> 4) * 16;

    const float* xg = x     + (size_t)m0 * ROWSTRIDE + (size_t)g * BIN;
    const float* Wg = g_Wtf + (size_t)g * (BOUT * BIN) + (size_t)n0 * BIN;

    float acc[4][8][4];                    // 128 regs: 64m x 64n per warp
    #pragma unroll
    for (int i = 0; i < 4; i++)
        #pragma unroll
        for (int j = 0; j < 8; j++)
            #pragma unroll
            for (int c = 0; c < 4; c++) acc[i][j][c] = 0.0f;

    auto load_stage = [&](int s, int ki) {
        const float* xk = xg + ki * BK;
        const float* wk = Wg + ki * BK;
        const uint32_t aS = smem_u32 + s * STAGE_BYTES;
        const uint32_t bS = aS + A_STAGE_BYTES;
        #pragma unroll
        for (int it = 0; it < (BM * 8) / THREADS; it++) {   // 4 / thread
            int id  = tid + it * THREADS;
            int row = id >> 3, ch = id & 7;
            cp16(aS + swz(row * 128 + ch * 16),
                 xk + (size_t)row * ROWSTRIDE + ch * 4);
        }
        #pragma unroll
        for (int it = 0; it < (BN * 8) / THREADS; it++) {   // 8 / thread
            int id  = tid + it * THREADS;
            int row = id >> 3, ch = id & 7;
            cp16(bS + swz(row * 128 + ch * 16),
                 wk + (size_t)row * BIN + ch * 4);
        }
    };

    #pragma unroll
    for (int s = 0; s < STAGES - 1; s++) { load_stage(s, s); cp_commit(); }

    int st = 0, ls = STAGES - 1;
    for (int ki = 0; ki < KITERS; ki++) {
        cp_wait<STAGES - 2>();
        __syncthreads();

        const uint32_t aS = smem_u32 + st * STAGE_BYTES;
        const uint32_t bS = aS + A_STAGE_BYTES;

        #pragma unroll
        for (int ks = 0; ks < BK; ks += 8) {
            uint32_t a[4][4], b[4][4];
            #pragma unroll
            for (int mf = 0; mf < 4; mf++)
                ldsm_x4(a[mf], aS + swz((uint32_t)(wm + mf * 16 + lrow) * 128
                                        + ks * 4 + lchunk));
            #pragma unroll
            for (int q = 0; q < 4; q++)
                ldsm_x4(b[q], bS + swz((uint32_t)(wn + q * 16 + lrow) * 128
                                       + ks * 4 + lchunk));
            // no cvt: x truncated by tf32 mma HW, W pre-rounded to tf32-RN
            #pragma unroll
            for (int mf = 0; mf < 4; mf++) {
                #pragma unroll
                for (int q = 0; q < 4; q++) {
                    mma_tf32(acc[mf][2 * q],     a[mf], b[q][0], b[q][2]);
                    mma_tf32(acc[mf][2 * q + 1], a[mf], b[q][1], b[q][3]);
                }
            }
        }

        int kload = ki + STAGES - 1;
        if (kload < KITERS) load_stage(ls, kload);
        cp_commit();

        st = (st == STAGES - 1) ? 0 : st + 1;
        ls = (ls == STAGES - 1) ? 0 : ls + 1;
    }

    // ---- epilogue: bias add + float2 stores ----
    #pragma unroll
    for (int mf = 0; mf < 4; mf++) {
        #pragma unroll
        for (int nf = 0; nf < 8; nf++) {
            int col = n0 + wn + nf * 8 + tig * 2;
            float bv0 = bias[g * BOUT + col];
            float bv1 = bias[g * BOUT + col + 1];
            int r0 = m0 + wm + mf * 16 + grp;
            float* p0 = out + (size_t)r0 * (NB * BOUT) + (size_t)g * BOUT + col;
            float* p1 = p0 + (size_t)8 * (NB * BOUT);
            float2 v0 = make_float2(acc[mf][nf][0] + bv0, acc[mf][nf][1] + bv1);
            float2 v1 = make_float2(acc[mf][nf][2] + bv0, acc[mf][nf][3] + bv1);
            *reinterpret_cast<float2*>(p0) = v0;
            *reinterpret_cast<float2*>(p1) = v1;
        }
    }
}

extern "C" void kernel_launch(void* const* d_in, const int* in_sizes, int n_in,
                              void* d_out, int out_size)
{
    const float* x = (const float*)d_in[0];
    const float* W = (const float*)d_in[1];
    const float* b = (const float*)d_in[2];
    float* out     = (float*)d_out;

    cudaFuncSetAttribute(block_linear_tf32_big,
                         cudaFuncAttributeMaxDynamicSharedMemorySize,
                         SMEM_BYTES);

    round_w_kernel<<<(NB * BOUT * BIN) / (256 * 4), 256>>>(W);

    dim3 grid(BOUT / BN, NB, BATCH / BM);   // (2, 8, 128)
    block_linear_tf32_big<<<grid, THREADS, SMEM_BYTES>>>(x, b, out);
}

// round 10
// speedup vs baseline: 1.5983x; 1.5983x over previous
#include <cuda_runtime.h>
#include <cstdint>

#define BATCH 16384
#define NB 8
#define BIN 512
#define BOUT 512
#define ROWSTRIDE 4096

#define BM 128
#define BN 128
#define BK 32
#define STAGES 3
#define THREADS 256
#define KITERS (BIN / BK)          // 16

#define A_STAGE_BYTES (BM * BK * 4)   // 16384
#define B_STAGE_BYTES (BN * BK * 4)   // 16384
#define SMEM_BYTES ((A_STAGE_BYTES + B_STAGE_BYTES) * STAGES)  // 98304

// W pre-rounded to tf32-RN (fp32 storage): no in-loop cvts.
__device__ float g_Wtf[NB * BOUT * BIN];

__device__ __forceinline__ uint32_t swz(uint32_t off) {
    return off ^ ((off >> 3) & 0x70);   // 128B-row xor swizzle
}

__device__ __forceinline__ void ldsm_x4(uint32_t* r, uint32_t addr) {
    asm volatile("ldmatrix.sync.aligned.m8n8.x4.shared.b16 {%0,%1,%2,%3}, [%4];"
                 : "=r"(r[0]), "=r"(r[1]), "=r"(r[2]), "=r"(r[3]) : "r"(addr));
}

__device__ __forceinline__ void cp16(uint32_t saddr, const void* g) {
    asm volatile("cp.async.cg.shared.global [%0], [%1], 16;" :: "r"(saddr), "l"(g));
}
__device__ __forceinline__ void cp_commit() {
    asm volatile("cp.async.commit_group;" ::: "memory");
}
template <int N>
__device__ __forceinline__ void cp_wait() {
    asm volatile("cp.async.wait_group %0;" :: "n"(N) : "memory");
}

__device__ __forceinline__ void mma_tf32(float* c, const uint32_t* a,
                                         uint32_t b0, uint32_t b1) {
    asm volatile(
        "mma.sync.aligned.m16n8k8.row.col.f32.tf32.tf32.f32 "
        "{%0,%1,%2,%3}, {%4,%5,%6,%7}, {%8,%9}, {%0,%1,%2,%3};"
        : "+f"(c[0]), "+f"(c[1]), "+f"(c[2]), "+f"(c[3])
        : "r"(a[0]), "r"(a[1]), "r"(a[2]), "r"(a[3]), "r"(b0), "r"(b1));
}

// ---- W pre-rounding: fp32 -> tf32-RN bits (fp32 storage) ----
__global__ void round_w_kernel(const float* __restrict__ W) {
    int i = (blockIdx.x * blockDim.x + threadIdx.x) * 4;
    float4 v = *reinterpret_cast<const float4*>(W + i);
    uint32_t r0, r1, r2, r3;
    asm("cvt.rna.tf32.f32 %0, %1;" : "=r"(r0) : "f"(v.x));
    asm("cvt.rna.tf32.f32 %0, %1;" : "=r"(r1) : "f"(v.y));
    asm("cvt.rna.tf32.f32 %0, %1;" : "=r"(r2) : "f"(v.z));
    asm("cvt.rna.tf32.f32 %0, %1;" : "=r"(r3) : "f"(v.w));
    float4 o = make_float4(__uint_as_float(r0), __uint_as_float(r1),
                           __uint_as_float(r2), __uint_as_float(r3));
    *reinterpret_cast<float4*>(g_Wtf + i) = o;
}

__global__ void __launch_bounds__(THREADS, 2)
block_linear_tf32_pf(const float* __restrict__ x,
                     const float* __restrict__ bias,
                     float* __restrict__ out)
{
    extern __shared__ uint8_t smem[];
    const uint32_t smem_u32 = (uint32_t)__cvta_generic_to_shared(smem);
    const uint32_t aBase = smem_u32;
    const uint32_t bBase = smem_u32 + STAGES * A_STAGE_BYTES;

    const int n0 = blockIdx.x * BN;        // n fastest -> L2 x-slice reuse
    const int g  = blockIdx.y;
    const int m0 = blockIdx.z * BM;

    const int tid  = threadIdx.x;
    const int warp = tid >> 5;
    const int lane = tid & 31;
    const int grp  = lane >> 2;
    const int tig  = lane & 3;

    const int wm = (warp & 3) * 32;        // 4 warps over M
    const int wn = (warp >> 2) * 64;       // 2 warps over N

    const int lrow   = lane & 15;
    const int lchunk = (lane >> 4) * 16;

    const float* xg = x     + (size_t)m0 * ROWSTRIDE + (size_t)g * BIN;
    const float* Wg = g_Wtf + (size_t)g * (BOUT * BIN) + (size_t)n0 * BIN;

    float acc[2][8][4];
    #pragma unroll
    for (int i = 0; i < 2; i++)
        #pragma unroll
        for (int j = 0; j < 8; j++)
            #pragma unroll
            for (int c = 0; c < 4; c++) acc[i][j][c] = 0.0f;

    auto load_stage = [&](int s, int ki) {
        const float* xk = xg + ki * BK;
        const float* wk = Wg + ki * BK;
        uint32_t aS = aBase + s * A_STAGE_BYTES;
        uint32_t bS = bBase + s * B_STAGE_BYTES;
        #pragma unroll
        for (int it = 0; it < (BM * 8) / THREADS; it++) {
            int id  = tid + it * THREADS;
            int row = id >> 3, ch = id & 7;
            cp16(aS + swz(row * 128 + ch * 16),
                 xk + (size_t)row * ROWSTRIDE + ch * 4);
        }
        #pragma unroll
        for (int it = 0; it < (BN * 8) / THREADS; it++) {
            int id  = tid + it * THREADS;
            int row = id >> 3, ch = id & 7;
            cp16(bS + swz(row * 128 + ch * 16),
                 wk + (size_t)row * BIN + ch * 4);
        }
    };

    // fragment load (6 ldmatrix) for one 8-wide k step
    uint32_t af[2][2][4], bf[2][4][4];     // double-buffered
    auto load_frags = [&](int buf, int ks, uint32_t aS, uint32_t bS) {
        #pragma unroll
        for (int mf = 0; mf < 2; mf++)
            ldsm_x4(af[buf][mf], aS + swz((uint32_t)(wm + mf * 16 + lrow) * 128
                                          + ks * 4 + lchunk));
        #pragma unroll
        for (int q = 0; q < 4; q++)
            ldsm_x4(bf[buf][q], bS + swz((uint32_t)(wn + q * 16 + lrow) * 128
                                         + ks * 4 + lchunk));
    };

    #pragma unroll
    for (int s = 0; s < STAGES - 1; s++) { load_stage(s, s); cp_commit(); }

    int st = 0, ls = STAGES - 1;
    for (int ki = 0; ki < KITERS; ki++) {
        cp_wait<STAGES - 2>();
        __syncthreads();

        const uint32_t aS = aBase + st * A_STAGE_BYTES;
        const uint32_t bS = bBase + st * B_STAGE_BYTES;

        // prime fragment pipeline for ks=0
        load_frags(0, 0, aS, bS);

        // issue next stage's gmem->smem loads BEFORE the mma block
        int kload = ki + STAGES - 1;
        if (kload < KITERS) load_stage(ls, kload);
        cp_commit();

        #pragma unroll
        for (int i = 0; i < BK / 8; i++) {
            const int cur = i & 1;
            if (i < BK / 8 - 1)
                load_frags(cur ^ 1, (i + 1) * 8, aS, bS);   // prefetch next
            #pragma unroll
            for (int mf = 0; mf < 2; mf++) {
                #pragma unroll
                for (int q = 0; q < 4; q++) {
                    mma_tf32(acc[mf][2 * q],     af[cur][mf], bf[cur][q][0], bf[cur][q][2]);
                    mma_tf32(acc[mf][2 * q + 1], af[cur][mf], bf[cur][q][1], bf[cur][q][3]);
                }
            }
        }

        st = (st == STAGES - 1) ? 0 : st + 1;
        ls = (ls == STAGES - 1) ? 0 : ls + 1;
    }

    // ---- epilogue: bias add + float2 stores ----
    #pragma unroll
    for (int mf = 0; mf < 2; mf++) {
        #pragma unroll
        for (int nf = 0; nf < 8; nf++) {
            int col = n0 + wn + nf * 8 + tig * 2;
            float bv0 = bias[g * BOUT + col];
            float bv1 = bias[g * BOUT + col + 1];
            int r0 = m0 + wm + mf * 16 + grp;
            float* p0 = out + (size_t)r0 * (NB * BOUT) + (size_t)g * BOUT + col;
            float* p1 = p0 + (size_t)8 * (NB * BOUT);
            float2 v0 = make_float2(acc[mf][nf][0] + bv0, acc[mf][nf][1] + bv1);
            float2 v1 = make_float2(acc[mf][nf][2] + bv0, acc[mf][nf][3] + bv1);
            *reinterpret_cast<float2*>(p0) = v0;
            *reinterpret_cast<float2*>(p1) = v1;
        }
    }
}

extern "C" void kernel_launch(void* const* d_in, const int* in_sizes, int n_in,
                              void* d_out, int out_size)
{
    const float* x = (const float*)d_in[0];
    const float* W = (const float*)d_in[1];
    const float* b = (const float*)d_in[2];
    float* out     = (float*)d_out;

    cudaFuncSetAttribute(block_linear_tf32_pf,
                         cudaFuncAttributeMaxDynamicSharedMemorySize,
                         SMEM_BYTES);

    round_w_kernel<<<(NB * BOUT * BIN) / (256 * 4), 256>>>(W);

    dim3 grid(BOUT / BN, NB, BATCH / BM);   // (4, 8, 128)
    block_linear_tf32_pf<<<grid, THREADS, SMEM_BYTES>>>(x, b, out);
}

// round 13
// speedup vs baseline: 1.7771x; 1.1119x over previous
#include <cuda_runtime.h>
#include <cstdint>

#define BATCH 16384
#define NB 8
#define BIN 512
#define BOUT 512
#define ROWSTRIDE 4096

#define BM 128
#define BN 128
#define BK 32
#define STAGES 3
#define THREADS 256
#define KITERS (BIN / BK)          // 16

#define A_STAGE_BYTES (BM * BK * 4)   // 16384
#define B_STAGE_BYTES (BN * BK * 4)   // 16384
#define SMEM_BYTES ((A_STAGE_BYTES + B_STAGE_BYTES) * STAGES)  // 98304

// W pre-rounded to tf32-RN (fp32 storage): no in-loop cvts.
__device__ float g_Wtf[NB * BOUT * BIN];

__device__ __forceinline__ uint32_t swz(uint32_t off) {
    return off ^ ((off >> 3) & 0x70);   // 128B-row xor swizzle
}

__device__ __forceinline__ void ldsm_x4(uint32_t* r, uint32_t addr) {
    asm volatile("ldmatrix.sync.aligned.m8n8.x4.shared.b16 {%0,%1,%2,%3}, [%4];"
                 : "=r"(r[0]), "=r"(r[1]), "=r"(r[2]), "=r"(r[3]) : "r"(addr));
}

__device__ __forceinline__ void cp16(uint32_t saddr, const void* g) {
    asm volatile("cp.async.cg.shared.global [%0], [%1], 16;" :: "r"(saddr), "l"(g));
}
__device__ __forceinline__ void cp_commit() {
    asm volatile("cp.async.commit_group;" ::: "memory");
}
template <int N>
__device__ __forceinline__ void cp_wait() {
    asm volatile("cp.async.wait_group %0;" :: "n"(N) : "memory");
}

__device__ __forceinline__ void mma_tf32(float* c, const uint32_t* a,
                                         uint32_t b0, uint32_t b1) {
    asm volatile(
        "mma.sync.aligned.m16n8k8.row.col.f32.tf32.tf32.f32 "
        "{%0,%1,%2,%3}, {%4,%5,%6,%7}, {%8,%9}, {%0,%1,%2,%3};"
        : "+f"(c[0]), "+f"(c[1]), "+f"(c[2]), "+f"(c[3])
        : "r"(a[0]), "r"(a[1]), "r"(a[2]), "r"(a[3]), "r"(b0), "r"(b1));
}

// ---- W pre-rounding: fp32 -> tf32-RN bits (fp32 storage) ----
__global__ void round_w_kernel(const float* __restrict__ W) {
    int i = (blockIdx.x * blockDim.x + threadIdx.x) * 4;
    float4 v = *reinterpret_cast<const float4*>(W + i);
    uint32_t r0, r1, r2, r3;
    asm("cvt.rna.tf32.f32 %0, %1;" : "=r"(r0) : "f"(v.x));
    asm("cvt.rna.tf32.f32 %0, %1;" : "=r"(r1) : "f"(v.y));
    asm("cvt.rna.tf32.f32 %0, %1;" : "=r"(r2) : "f"(v.z));
    asm("cvt.rna.tf32.f32 %0, %1;" : "=r"(r3) : "f"(v.w));
    float4 o = make_float4(__uint_as_float(r0), __uint_as_float(r1),
                           __uint_as_float(r2), __uint_as_float(r3));
    *reinterpret_cast<float4*>(g_Wtf + i) = o;
}

__global__ void __launch_bounds__(THREADS, 2)
block_linear_tf32_pipe(const float* __restrict__ x,
                       const float* __restrict__ bias,
                       float* __restrict__ out)
{
    extern __shared__ uint8_t smem[];
    const uint32_t smem_u32 = (uint32_t)__cvta_generic_to_shared(smem);
    const uint32_t aBase = smem_u32;
    const uint32_t bBase = smem_u32 + STAGES * A_STAGE_BYTES;

    const int n0 = blockIdx.x * BN;        // n fastest -> L2 x-slice reuse
    const int g  = blockIdx.y;
    const int m0 = blockIdx.z * BM;

    const int tid  = threadIdx.x;
    const int warp = tid >> 5;
    const int lane = tid & 31;
    const int grp  = lane >> 2;
    const int tig  = lane & 3;

    const int wm = (warp & 3) * 32;        // 4 warps over M
    const int wn = (warp >> 2) * 64;       // 2 warps over N

    const int lrow   = lane & 15;
    const int lchunk = (lane >> 4) * 16;

    const float* xg = x     + (size_t)m0 * ROWSTRIDE + (size_t)g * BIN;
    const float* Wg = g_Wtf + (size_t)g * (BOUT * BIN) + (size_t)n0 * BIN;

    float acc[2][8][4];
    #pragma unroll
    for (int i = 0; i < 2; i++)
        #pragma unroll
        for (int j = 0; j < 8; j++)
            #pragma unroll
            for (int c = 0; c < 4; c++) acc[i][j][c] = 0.0f;

    auto load_stage = [&](int s, int ki) {
        const float* xk = xg + ki * BK;
        const float* wk = Wg + ki * BK;
        uint32_t aS = aBase + s * A_STAGE_BYTES;
        uint32_t bS = bBase + s * B_STAGE_BYTES;
        #pragma unroll
        for (int it = 0; it < (BM * 8) / THREADS; it++) {
            int id  = tid + it * THREADS;
            int row = id >> 3, ch = id & 7;
            cp16(aS + swz(row * 128 + ch * 16),
                 xk + (size_t)row * ROWSTRIDE + ch * 4);
        }
        #pragma unroll
        for (int it = 0; it < (BN * 8) / THREADS; it++) {
            int id  = tid + it * THREADS;
            int row = id >> 3, ch = id & 7;
            cp16(bS + swz(row * 128 + ch * 16),
                 wk + (size_t)row * BIN + ch * 4);
        }
    };

    #pragma unroll
    for (int s = 0; s < STAGES - 1; s++) { load_stage(s, s); cp_commit(); }

    int st = 0, ls = STAGES - 1;
    for (int ki = 0; ki < KITERS; ki++) {
        cp_wait<STAGES - 2>();
        __syncthreads();

        // Issue next stage's gmem->smem loads BEFORE the mma block so the
        // memory latency overlaps compute. Safe: the target stage ls was
        // last read in iteration ki-1, fully drained by the barrier above.
        int kload = ki + STAGES - 1;
        if (kload < KITERS) load_stage(ls, kload);
        cp_commit();

        const uint32_t aS = aBase + st * A_STAGE_BYTES;
        const uint32_t bS = bBase + st * B_STAGE_BYTES;

        #pragma unroll
        for (int ks = 0; ks < BK; ks += 8) {
            uint32_t a[2][4], b[4][4];
            #pragma unroll
            for (int mf = 0; mf < 2; mf++)
                ldsm_x4(a[mf], aS + swz((uint32_t)(wm + mf * 16 + lrow) * 128
                                        + ks * 4 + lchunk));
            #pragma unroll
            for (int q = 0; q < 4; q++)
                ldsm_x4(b[q], bS + swz((uint32_t)(wn + q * 16 + lrow) * 128
                                       + ks * 4 + lchunk));
            // no cvt: x truncated by tf32 mma HW, W pre-rounded to tf32-RN
            #pragma unroll
            for (int mf = 0; mf < 2; mf++) {
                #pragma unroll
                for (int q = 0; q < 4; q++) {
                    mma_tf32(acc[mf][2 * q],     a[mf], b[q][0], b[q][2]);
                    mma_tf32(acc[mf][2 * q + 1], a[mf], b[q][1], b[q][3]);
                }
            }
        }

        st = (st == STAGES - 1) ? 0 : st + 1;
        ls = (ls == STAGES - 1) ? 0 : ls + 1;
    }

    // ---- epilogue: bias add + float2 stores ----
    #pragma unroll
    for (int mf = 0; mf < 2; mf++) {
        #pragma unroll
        for (int nf = 0; nf < 8; nf++) {
            int col = n0 + wn + nf * 8 + tig * 2;
            float bv0 = bias[g * BOUT + col];
            float bv1 = bias[g * BOUT + col + 1];
            int r0 = m0 + wm + mf * 16 + grp;
            float* p0 = out + (size_t)r0 * (NB * BOUT) + (size_t)g * BOUT + col;
            float* p1 = p0 + (size_t)8 * (NB * BOUT);
            float2 v0 = make_float2(acc[mf][nf][0] + bv0, acc[mf][nf][1] + bv1);
            float2 v1 = make_float2(acc[mf][nf][2] + bv0, acc[mf][nf][3] + bv1);
            *reinterpret_cast<float2*>(p0) = v0;
            *reinterpret_cast<float2*>(p1) = v1;
        }
    }
}

extern "C" void kernel_launch(void* const* d_in, const int* in_sizes, int n_in,
                              void* d_out, int out_size)
{
    const float* x = (const float*)d_in[0];
    const float* W = (const float*)d_in[1];
    const float* b = (const float*)d_in[2];
    float* out     = (float*)d_out;

    cudaFuncSetAttribute(block_linear_tf32_pipe,
                         cudaFuncAttributeMaxDynamicSharedMemorySize,
                         SMEM_BYTES);

    round_w_kernel<<<(NB * BOUT * BIN) / (256 * 4), 256>>>(W);

    dim3 grid(BOUT / BN, NB, BATCH / BM);   // (4, 8, 128)
    block_linear_tf32_pipe<<<grid, THREADS, SMEM_BYTES>>>(x, b, out);
}